// round 1
// baseline (speedup 1.0000x reference)
#include <cuda_runtime.h>
#include <cuda_bf16.h>
#include <mma.h>

using namespace nvcuda;

#define NB   4        // batch
#define HW   4096     // h*w
#define CH   512      // channels
#define NGRP 32
#define CPG  16       // channels per group
#define GNEPS 1e-5f

// ---------------- scratch (static __device__, no allocations) ----------------
__device__ float g_h[(long)NB * HW * CH];        // normalized input
__device__ float g_q[(long)NB * HW * CH];
__device__ float g_k[(long)NB * HW * CH];
__device__ float g_v[(long)NB * HW * CH];
__device__ float g_ao[(long)NB * HW * CH];       // attention output
__device__ float g_scores[(long)NB * HW * HW];   // 256 MB
__device__ float g_mean[NB * NGRP];
__device__ float g_rstd[NB * NGRP];

// ---------------- GroupNorm: stats ----------------
__global__ __launch_bounds__(256) void gn_stats(const float* __restrict__ x) {
    int bid = blockIdx.x;            // b*32 + g
    int b = bid >> 5, g = bid & 31;
    const float* base = x + (long)b * HW * CH + g * CPG;
    float s = 0.f, ss = 0.f;
    for (int p = threadIdx.x; p < HW; p += 256) {
        const float4* pp = (const float4*)(base + (long)p * CH);
#pragma unroll
        for (int i = 0; i < 4; i++) {
            float4 v = pp[i];
            s  += v.x + v.y + v.z + v.w;
            ss += v.x * v.x + v.y * v.y + v.z * v.z + v.w * v.w;
        }
    }
    __shared__ float sh[512];
    sh[threadIdx.x] = s; sh[256 + threadIdx.x] = ss;
    __syncthreads();
    for (int o = 128; o > 0; o >>= 1) {
        if (threadIdx.x < o) {
            sh[threadIdx.x] += sh[threadIdx.x + o];
            sh[256 + threadIdx.x] += sh[256 + threadIdx.x + o];
        }
        __syncthreads();
    }
    if (threadIdx.x == 0) {
        const float inv = 1.0f / (HW * CPG);
        float mean = sh[0] * inv;
        float var  = sh[256] * inv - mean * mean;
        g_mean[bid] = mean;
        g_rstd[bid] = rsqrtf(var + GNEPS);
    }
}

// ---------------- GroupNorm: apply ----------------
__global__ __launch_bounds__(256) void gn_apply(const float* __restrict__ x,
                                                const float* __restrict__ gamma,
                                                const float* __restrict__ beta) {
    long i = (long)blockIdx.x * 256 + threadIdx.x;    // float4 index
    long i4 = i * 4;
    int b = (int)(i4 >> 21);                          // HW*CH = 2^21
    int c = (int)(i4 & (CH - 1));
    int g = c >> 4;
    float mean = g_mean[b * NGRP + g];
    float rstd = g_rstd[b * NGRP + g];
    float4 v  = ((const float4*)x)[i];
    float4 ga = ((const float4*)gamma)[c >> 2];
    float4 be = ((const float4*)beta)[c >> 2];
    float4 o;
    o.x = (v.x - mean) * rstd * ga.x + be.x;
    o.y = (v.y - mean) * rstd * ga.y + be.y;
    o.z = (v.z - mean) * rstd * ga.z + be.z;
    o.w = (v.w - mean) * rstd * ga.w + be.w;
    ((float4*)g_h)[i] = o;
}

// ---------------- TF32 WMMA GEMM  C = alpha*A@B (+bias) (+res) --------------
// A: [M,K] row-major.  B: row-major [K,N] (BCOL=false) or B is [N,K] row-major
// interpreted as col-major K x N (BCOL=true, i.e. C = A @ B^T).
// Tiles: BM=128 BN=64 BK=16, 8 warps, warp tile 32x32 (2x2 of m16n16k8).
template<bool BCOL, bool BIAS, bool RES>
__global__ __launch_bounds__(256)
void gemm_tf32(const float* __restrict__ A, const float* __restrict__ Bm,
               const float* __restrict__ bias, const float* __restrict__ res,
               float* __restrict__ Cm,
               int M, int N, int K,
               long sA, long sB, long sC, float alpha) {
    const int bz = blockIdx.z;
    A  += (long)bz * sA;
    Bm += (long)bz * sB;
    Cm += (long)bz * sC;
    const float* resp = RES ? (res + (long)bz * sC) : nullptr;

    const int lda = K;
    const int ldb = BCOL ? K : N;
    const int ldc = N;
    const int bm = blockIdx.y * 128;
    const int bn = blockIdx.x * 64;

    __shared__ float smem[9216];              // tiles (4224 used) / epilogue (9216)
    float* As = smem;                          // [128][24]
    float* Bs = smem + 128 * 24;               // [16][72]

    const int tid = threadIdx.x;
    const int warp = tid >> 5, lane = tid & 31;
    const int wm = warp >> 1, wn = warp & 1;

    wmma::fragment<wmma::accumulator, 16, 16, 8, float> acc[2][2];
#pragma unroll
    for (int i = 0; i < 2; i++)
#pragma unroll
        for (int j = 0; j < 2; j++) wmma::fill_fragment(acc[i][j], 0.0f);

    for (int k0 = 0; k0 < K; k0 += 16) {
        // stage A tile 128x16
#pragma unroll
        for (int r = 0; r < 2; r++) {
            int idx = tid + r * 256;               // 0..511
            int row = idx >> 2, c4 = idx & 3;
            float4 v = *(const float4*)(A + (long)(bm + row) * lda + k0 + c4 * 4);
            *(float4*)(As + row * 24 + c4 * 4) = v;
        }
        // stage B tile 16x64
        if (BCOL) {
            int n = tid >> 2, c4 = tid & 3;
            float4 v = *(const float4*)(Bm + (long)(bn + n) * ldb + k0 + c4 * 4);
            Bs[(c4 * 4 + 0) * 72 + n] = v.x;
            Bs[(c4 * 4 + 1) * 72 + n] = v.y;
            Bs[(c4 * 4 + 2) * 72 + n] = v.z;
            Bs[(c4 * 4 + 3) * 72 + n] = v.w;
        } else {
            int row = tid >> 4, c4 = tid & 15;
            float4 v = *(const float4*)(Bm + (long)(k0 + row) * ldb + bn + c4 * 4);
            *(float4*)(Bs + row * 72 + c4 * 4) = v;
        }
        __syncthreads();

#pragma unroll
        for (int kk = 0; kk < 16; kk += 8) {
            wmma::fragment<wmma::matrix_a, 16, 16, 8, wmma::precision::tf32, wmma::row_major> af[2];
            wmma::fragment<wmma::matrix_b, 16, 16, 8, wmma::precision::tf32, wmma::row_major> bf[2];
#pragma unroll
            for (int i = 0; i < 2; i++) {
                wmma::load_matrix_sync(af[i], As + (wm * 32 + i * 16) * 24 + kk, 24);
#pragma unroll
                for (int t = 0; t < af[i].num_elements; t++)
                    af[i].x[t] = wmma::__float_to_tf32(af[i].x[t]);
            }
#pragma unroll
            for (int j = 0; j < 2; j++) {
                wmma::load_matrix_sync(bf[j], Bs + kk * 72 + wn * 32 + j * 16, 72);
#pragma unroll
                for (int t = 0; t < bf[j].num_elements; t++)
                    bf[j].x[t] = wmma::__float_to_tf32(bf[j].x[t]);
            }
#pragma unroll
            for (int i = 0; i < 2; i++)
#pragma unroll
                for (int j = 0; j < 2; j++)
                    wmma::mma_sync(acc[i][j], af[i], bf[j], acc[i][j]);
        }
        __syncthreads();
    }

    // epilogue: per-warp 32x36 staging, then scaled/bias/residual store
    float* buf = smem + warp * 1152;
#pragma unroll
    for (int i = 0; i < 2; i++)
#pragma unroll
        for (int j = 0; j < 2; j++)
            wmma::store_matrix_sync(buf + i * 16 * 36 + j * 16, acc[i][j], 36,
                                    wmma::mem_row_major);
    __syncwarp();
    const int gn = bn + wn * 32 + lane;
    const float bval = BIAS ? bias[gn] : 0.0f;
#pragma unroll 4
    for (int r = 0; r < 32; r++) {
        int gm = bm + wm * 32 + r;
        float v = buf[r * 36 + lane] * alpha + bval;
        if (RES) v += resp[(long)gm * ldc + gn];
        Cm[(long)gm * ldc + gn] = v;
    }
}

// ---------------- row softmax over 4096 columns ----------------
__global__ __launch_bounds__(256) void softmax_rows(float* __restrict__ sc) {
    long row = blockIdx.x;
    float* p = sc + row * (long)HW;
    int tid = threadIdx.x;
    float4 v[4];
    float mx = -1e30f;
#pragma unroll
    for (int i = 0; i < 4; i++) {
        v[i] = ((float4*)p)[i * 256 + tid];
        mx = fmaxf(mx, fmaxf(fmaxf(v[i].x, v[i].y), fmaxf(v[i].z, v[i].w)));
    }
    __shared__ float sh[256];
    sh[tid] = mx; __syncthreads();
    for (int o = 128; o > 0; o >>= 1) {
        if (tid < o) sh[tid] = fmaxf(sh[tid], sh[tid + o]);
        __syncthreads();
    }
    mx = sh[0];
    __syncthreads();
    float s = 0.f;
#pragma unroll
    for (int i = 0; i < 4; i++) {
        v[i].x = __expf(v[i].x - mx); v[i].y = __expf(v[i].y - mx);
        v[i].z = __expf(v[i].z - mx); v[i].w = __expf(v[i].w - mx);
        s += v[i].x + v[i].y + v[i].z + v[i].w;
    }
    sh[tid] = s; __syncthreads();
    for (int o = 128; o > 0; o >>= 1) {
        if (tid < o) sh[tid] += sh[tid + o];
        __syncthreads();
    }
    float inv = 1.0f / sh[0];
#pragma unroll
    for (int i = 0; i < 4; i++) {
        v[i].x *= inv; v[i].y *= inv; v[i].z *= inv; v[i].w *= inv;
        ((float4*)p)[i * 256 + tid] = v[i];
    }
}

// ---------------- launch ----------------
extern "C" void kernel_launch(void* const* d_in, const int* in_sizes, int n_in,
                              void* d_out, int out_size) {
    const float* x     = (const float*)d_in[0];
    const float* gamma = (const float*)d_in[1];
    const float* beta  = (const float*)d_in[2];
    const float* wq = (const float*)d_in[3];
    const float* bq = (const float*)d_in[4];
    const float* wk = (const float*)d_in[5];
    const float* bk = (const float*)d_in[6];
    const float* wv = (const float*)d_in[7];
    const float* bv = (const float*)d_in[8];
    const float* wp = (const float*)d_in[9];
    const float* bp = (const float*)d_in[10];
    float* out = (float*)d_out;

    float* hh = nullptr, *qq = nullptr, *kk = nullptr, *vv = nullptr,
         * ao = nullptr, *sc = nullptr;
    cudaGetSymbolAddress((void**)&hh, g_h);
    cudaGetSymbolAddress((void**)&qq, g_q);
    cudaGetSymbolAddress((void**)&kk, g_k);
    cudaGetSymbolAddress((void**)&vv, g_v);
    cudaGetSymbolAddress((void**)&ao, g_ao);
    cudaGetSymbolAddress((void**)&sc, g_scores);

    const long sQ = (long)HW * CH;       // per-batch q/k/v stride
    const long sS = (long)HW * HW;       // per-batch scores stride
    const float scale = 0.044194173824159216f;   // 1/sqrt(512)

    // 1) GroupNorm
    gn_stats<<<NB * NGRP, 256>>>(x);
    gn_apply<<<(NB * HW * CH / 4) / 256, 256>>>(x, gamma, beta);

    // 2) QKV projections: [16384,512] @ [512,512] + bias
    gemm_tf32<false, true, false><<<dim3(CH / 64, (NB * HW) / 128, 1), 256>>>(
        hh, wq, bq, nullptr, qq, NB * HW, CH, CH, 0, 0, 0, 1.0f);
    gemm_tf32<false, true, false><<<dim3(CH / 64, (NB * HW) / 128, 1), 256>>>(
        hh, wk, bk, nullptr, kk, NB * HW, CH, CH, 0, 0, 0, 1.0f);
    gemm_tf32<false, true, false><<<dim3(CH / 64, (NB * HW) / 128, 1), 256>>>(
        hh, wv, bv, nullptr, vv, NB * HW, CH, CH, 0, 0, 0, 1.0f);

    // 3) scores = scale * q @ k^T   (per batch)
    gemm_tf32<true, false, false><<<dim3(HW / 64, HW / 128, NB), 256>>>(
        qq, kk, nullptr, nullptr, sc, HW, HW, CH, sQ, sQ, sS, scale);

    // 4) softmax rows
    softmax_rows<<<NB * HW, 256>>>(sc);

    // 5) attn @ v   (per batch)
    gemm_tf32<false, false, false><<<dim3(CH / 64, HW / 128, NB), 256>>>(
        sc, vv, nullptr, nullptr, ao, HW, CH, HW, sS, sQ, sQ, 1.0f);

    // 6) proj + residual
    gemm_tf32<false, true, true><<<dim3(CH / 64, (NB * HW) / 128, 1), 256>>>(
        ao, wp, bp, x, out, NB * HW, CH, CH, 0, 0, 0, 1.0f);
}

// round 6
// speedup vs baseline: 1.1859x; 1.1859x over previous
#include <cuda_runtime.h>
#include <mma.h>

using namespace nvcuda;

#define NB   4
#define HW   4096
#define CH   512
#define QKVN 1536
#define NGRP 32
#define CPG  16
#define GNEPS 1e-5f

// ---------------- scratch ----------------
__device__ float g_h[(long)NB * HW * CH];          // normalized (tf32-rounded)
__device__ float g_qkv[(long)NB * HW * QKVN];      // q|k|v interleaved per row
__device__ float g_ao[(long)NB * HW * CH];
__device__ float g_scores[(long)NB * HW * HW];     // 256 MB
__device__ float g_wqkv[CH * QKVN];                // rounded concat weights
__device__ float g_bqkv[QKVN];
__device__ float g_wpr[CH * CH];                   // rounded proj weight
__device__ float g_mean[NB * NGRP];
__device__ float g_rstd[NB * NGRP];

__device__ __forceinline__ float tf32r(float x) { return wmma::__float_to_tf32(x); }

__device__ __forceinline__ void cpa16(float* s, const float* g) {
    unsigned sa = (unsigned)__cvta_generic_to_shared(s);
    asm volatile("cp.async.cg.shared.global [%0], [%1], 16;" :: "r"(sa), "l"(g));
}

// ---------------- weight prep: concat + tf32 round ----------------
__global__ __launch_bounds__(256) void prep(const float* __restrict__ wq,
                                            const float* __restrict__ wk,
                                            const float* __restrict__ wv,
                                            const float* __restrict__ wp,
                                            const float* __restrict__ bq,
                                            const float* __restrict__ bk,
                                            const float* __restrict__ bv) {
    int idx = blockIdx.x * 256 + threadIdx.x;
    if (idx < CH * QKVN) {
        int c = idx / QKVN, col = idx - c * QKVN;
        int sel = col >> 9, cc = col & 511;
        const float* w = (sel == 0) ? wq : (sel == 1) ? wk : wv;
        g_wqkv[idx] = tf32r(w[c * CH + cc]);
        if (idx < QKVN) {
            const float* bb = (idx < 512) ? bq : (idx < 1024) ? bk : bv;
            g_bqkv[idx] = bb[idx & 511];
        }
    } else {
        int j = idx - CH * QKVN;
        if (j < CH * CH) g_wpr[j] = tf32r(wp[j]);
    }
}

// ---------------- GroupNorm stats ----------------
__global__ __launch_bounds__(256) void gn_stats(const float* __restrict__ x) {
    int bid = blockIdx.x;
    int b = bid >> 5, g = bid & 31;
    const float* base = x + (long)b * HW * CH + g * CPG;
    float s = 0.f, ss = 0.f;
    for (int p = threadIdx.x; p < HW; p += 256) {
        const float4* pp = (const float4*)(base + (long)p * CH);
#pragma unroll
        for (int i = 0; i < 4; i++) {
            float4 v = pp[i];
            s  += v.x + v.y + v.z + v.w;
            ss += v.x * v.x + v.y * v.y + v.z * v.z + v.w * v.w;
        }
    }
    __shared__ float sh[512];
    sh[threadIdx.x] = s; sh[256 + threadIdx.x] = ss;
    __syncthreads();
    for (int o = 128; o > 0; o >>= 1) {
        if (threadIdx.x < o) {
            sh[threadIdx.x] += sh[threadIdx.x + o];
            sh[256 + threadIdx.x] += sh[256 + threadIdx.x + o];
        }
        __syncthreads();
    }
    if (threadIdx.x == 0) {
        const float inv = 1.0f / (HW * CPG);
        float mean = sh[0] * inv;
        float var  = sh[256] * inv - mean * mean;
        g_mean[bid] = mean;
        g_rstd[bid] = rsqrtf(var + GNEPS);
    }
}

// ---------------- GroupNorm apply (writes tf32-rounded) ----------------
__global__ __launch_bounds__(256) void gn_apply(const float* __restrict__ x,
                                                const float* __restrict__ gamma,
                                                const float* __restrict__ beta) {
    long i = (long)blockIdx.x * 256 + threadIdx.x;
    long i4 = i * 4;
    int b = (int)(i4 >> 21);
    int c = (int)(i4 & (CH - 1));
    int g = c >> 4;
    float mean = g_mean[b * NGRP + g];
    float rstd = g_rstd[b * NGRP + g];
    float4 v  = ((const float4*)x)[i];
    float4 ga = ((const float4*)gamma)[c >> 2];
    float4 be = ((const float4*)beta)[c >> 2];
    float4 o;
    o.x = tf32r((v.x - mean) * rstd * ga.x + be.x);
    o.y = tf32r((v.y - mean) * rstd * ga.y + be.y);
    o.z = tf32r((v.z - mean) * rstd * ga.z + be.z);
    o.w = tf32r((v.w - mean) * rstd * ga.w + be.w);
    ((float4*)g_h)[i] = o;
}

// ---------------- TF32 GEMM: 128x128x16 block, 8 warps, 64x32 warp tile -----
// Inputs must already be tf32-rounded. C = alpha*A@op(B) (+bias) (+res) (round)
// BCOL: B is [N,K] row-major, used as col-major KxN (C = A @ B^T).
template<bool BCOL, bool BIAS, bool RES, bool RND>
__global__ __launch_bounds__(256)
void gemm_tf32(const float* __restrict__ A, const float* __restrict__ B,
               const float* __restrict__ bias, const float* __restrict__ res,
               float* __restrict__ C,
               int lda, int ldb, int ldc,
               long sA, long sB, long sC, int K, float alpha) {
    __shared__ __align__(16) float As[2 * 128 * 20];   // [buf][row][20]
    __shared__ __align__(16) float Bs[2 * 128 * 20];   // BCOL: [buf][n][20]; else [buf][16][132]

    const int bz = blockIdx.z;
    A += (long)bz * sA;  B += (long)bz * sB;  C += (long)bz * sC;
    const float* resp = RES ? (res + (long)bz * sC) : nullptr;

    const int bm = blockIdx.y * 128, bn = blockIdx.x * 128;
    const int tid = threadIdx.x, warp = tid >> 5, lane = tid & 31;
    const int wm = warp >> 2, wn = warp & 3;

    // staging addresses
    const int arow = tid >> 2, ac4 = (tid & 3) * 4;
    const float* agp = A + (long)(bm + arow) * lda + ac4;
    const float* bgp_c = B + (long)(bn + arow) * ldb + ac4;          // BCOL
    const int brow = tid >> 5, bc4 = (tid & 31) * 4;
    const float* bgp_r = B + (long)brow * ldb + bn + bc4;            // !BCOL

    wmma::fragment<wmma::accumulator, 16, 16, 8, float> acc[4][2];
#pragma unroll
    for (int i = 0; i < 4; i++)
#pragma unroll
        for (int j = 0; j < 2; j++) wmma::fill_fragment(acc[i][j], 0.0f);

    auto stage = [&](int kt, int buf) {
        const float* ag = agp + kt * 16;
        cpa16(As + buf * 2560 + arow * 20 + ac4, ag);
        cpa16(As + buf * 2560 + (arow + 64) * 20 + ac4, ag + (long)64 * lda);
        if (BCOL) {
            const float* bg = bgp_c + kt * 16;
            cpa16(Bs + buf * 2560 + arow * 20 + ac4, bg);
            cpa16(Bs + buf * 2560 + (arow + 64) * 20 + ac4, bg + (long)64 * ldb);
        } else {
            const float* bg = bgp_r + (long)kt * 16 * ldb;
            cpa16(Bs + buf * 2112 + brow * 132 + bc4, bg);
            cpa16(Bs + buf * 2112 + (brow + 8) * 132 + bc4, bg + (long)8 * ldb);
        }
        asm volatile("cp.async.commit_group;" ::: "memory");
    };

    auto compute = [&](int buf) {
#pragma unroll
        for (int kk = 0; kk < 16; kk += 8) {
            wmma::fragment<wmma::matrix_a, 16, 16, 8, wmma::precision::tf32, wmma::row_major> af[4];
#pragma unroll
            for (int i = 0; i < 4; i++)
                wmma::load_matrix_sync(af[i], As + buf * 2560 + (wm * 64 + i * 16) * 20 + kk, 20);
            if constexpr (BCOL) {
                wmma::fragment<wmma::matrix_b, 16, 16, 8, wmma::precision::tf32, wmma::col_major> bf[2];
#pragma unroll
                for (int j = 0; j < 2; j++)
                    wmma::load_matrix_sync(bf[j], Bs + buf * 2560 + (wn * 32 + j * 16) * 20 + kk, 20);
#pragma unroll
                for (int i = 0; i < 4; i++)
#pragma unroll
                    for (int j = 0; j < 2; j++)
                        wmma::mma_sync(acc[i][j], af[i], bf[j], acc[i][j]);
            } else {
                wmma::fragment<wmma::matrix_b, 16, 16, 8, wmma::precision::tf32, wmma::row_major> bf[2];
#pragma unroll
                for (int j = 0; j < 2; j++)
                    wmma::load_matrix_sync(bf[j], Bs + buf * 2112 + kk * 132 + wn * 32 + j * 16, 132);
#pragma unroll
                for (int i = 0; i < 4; i++)
#pragma unroll
                    for (int j = 0; j < 2; j++)
                        wmma::mma_sync(acc[i][j], af[i], bf[j], acc[i][j]);
            }
        }
    };

    const int KT = K >> 4;
    stage(0, 0);
    for (int kt = 0; kt < KT; kt++) {
        const int buf = kt & 1;
        if (kt + 1 < KT) {
            stage(kt + 1, buf ^ 1);
            asm volatile("cp.async.wait_group 1;" ::: "memory");
        } else {
            asm volatile("cp.async.wait_group 0;" ::: "memory");
        }
        __syncthreads();
        compute(buf);
        __syncthreads();
    }

    // ---------------- epilogue: fragment-wise staging ----------------
    float* buf = As + warp * 320;                 // 16x20 per warp
    const int r = lane >> 1, cb = (lane & 1) * 8;
#pragma unroll
    for (int i = 0; i < 4; i++) {
#pragma unroll
        for (int j = 0; j < 2; j++) {
            wmma::store_matrix_sync(buf, acc[i][j], 20, wmma::mem_row_major);
            __syncwarp();
            float4 v0 = *(const float4*)(buf + r * 20 + cb);
            float4 v1 = *(const float4*)(buf + r * 20 + cb + 4);
            __syncwarp();
            const int gm = bm + wm * 64 + i * 16 + r;
            const int gnc = bn + wn * 32 + j * 16 + cb;
            float4 b0, b1;
            if (BIAS) {
                b0 = *(const float4*)(bias + gnc);
                b1 = *(const float4*)(bias + gnc + 4);
            }
            float4 o0, o1;
            o0.x = v0.x * alpha; o0.y = v0.y * alpha; o0.z = v0.z * alpha; o0.w = v0.w * alpha;
            o1.x = v1.x * alpha; o1.y = v1.y * alpha; o1.z = v1.z * alpha; o1.w = v1.w * alpha;
            if (BIAS) {
                o0.x += b0.x; o0.y += b0.y; o0.z += b0.z; o0.w += b0.w;
                o1.x += b1.x; o1.y += b1.y; o1.z += b1.z; o1.w += b1.w;
            }
            if (RES) {
                float4 r0 = *(const float4*)(resp + (long)gm * ldc + gnc);
                float4 r1 = *(const float4*)(resp + (long)gm * ldc + gnc + 4);
                o0.x += r0.x; o0.y += r0.y; o0.z += r0.z; o0.w += r0.w;
                o1.x += r1.x; o1.y += r1.y; o1.z += r1.z; o1.w += r1.w;
            }
            if (RND) {
                o0.x = tf32r(o0.x); o0.y = tf32r(o0.y); o0.z = tf32r(o0.z); o0.w = tf32r(o0.w);
                o1.x = tf32r(o1.x); o1.y = tf32r(o1.y); o1.z = tf32r(o1.z); o1.w = tf32r(o1.w);
            }
            *(float4*)(C + (long)gm * ldc + gnc)     = o0;
            *(float4*)(C + (long)gm * ldc + gnc + 4) = o1;
        }
    }
}

// ---------------- row softmax, writes tf32-rounded ----------------
__global__ __launch_bounds__(256) void softmax_rows(float* __restrict__ sc) {
    long row = blockIdx.x;
    float* p = sc + row * (long)HW;
    int tid = threadIdx.x;
    float4 v[4];
    float mx = -1e30f;
#pragma unroll
    for (int i = 0; i < 4; i++) {
        v[i] = ((float4*)p)[i * 256 + tid];
        mx = fmaxf(mx, fmaxf(fmaxf(v[i].x, v[i].y), fmaxf(v[i].z, v[i].w)));
    }
    __shared__ float sh[256];
    sh[tid] = mx; __syncthreads();
    for (int o = 128; o > 0; o >>= 1) {
        if (tid < o) sh[tid] = fmaxf(sh[tid], sh[tid + o]);
        __syncthreads();
    }
    mx = sh[0];
    __syncthreads();
    float s = 0.f;
#pragma unroll
    for (int i = 0; i < 4; i++) {
        v[i].x = __expf(v[i].x - mx); v[i].y = __expf(v[i].y - mx);
        v[i].z = __expf(v[i].z - mx); v[i].w = __expf(v[i].w - mx);
        s += v[i].x + v[i].y + v[i].z + v[i].w;
    }
    sh[tid] = s; __syncthreads();
    for (int o = 128; o > 0; o >>= 1) {
        if (tid < o) sh[tid] += sh[tid + o];
        __syncthreads();
    }
    float inv = 1.0f / sh[0];
#pragma unroll
    for (int i = 0; i < 4; i++) {
        v[i].x = tf32r(v[i].x * inv); v[i].y = tf32r(v[i].y * inv);
        v[i].z = tf32r(v[i].z * inv); v[i].w = tf32r(v[i].w * inv);
        ((float4*)p)[i * 256 + tid] = v[i];
    }
}

// ---------------- launch ----------------
extern "C" void kernel_launch(void* const* d_in, const int* in_sizes, int n_in,
                              void* d_out, int out_size) {
    const float* x     = (const float*)d_in[0];
    const float* gamma = (const float*)d_in[1];
    const float* beta  = (const float*)d_in[2];
    const float* wq = (const float*)d_in[3];
    const float* bq = (const float*)d_in[4];
    const float* wk = (const float*)d_in[5];
    const float* bk = (const float*)d_in[6];
    const float* wv = (const float*)d_in[7];
    const float* bv = (const float*)d_in[8];
    const float* wp = (const float*)d_in[9];
    const float* bp = (const float*)d_in[10];
    float* out = (float*)d_out;

    float *hh, *qkv, *ao, *sc, *wqkvp, *bqkvp, *wpr;
    cudaGetSymbolAddress((void**)&hh, g_h);
    cudaGetSymbolAddress((void**)&qkv, g_qkv);
    cudaGetSymbolAddress((void**)&ao, g_ao);
    cudaGetSymbolAddress((void**)&sc, g_scores);
    cudaGetSymbolAddress((void**)&wqkvp, g_wqkv);
    cudaGetSymbolAddress((void**)&bqkvp, g_bqkv);
    cudaGetSymbolAddress((void**)&wpr, g_wpr);

    const long sQ = (long)HW * QKVN;
    const long sS = (long)HW * HW;
    const long sO = (long)HW * CH;
    const float scale = 0.044194173824159216f;   // 1/sqrt(512)

    // 0) weight prep (round + concat)
    prep<<<(CH * QKVN + CH * CH) / 256, 256>>>(wq, wk, wv, wp, bq, bk, bv);

    // 1) GroupNorm
    gn_stats<<<NB * NGRP, 256>>>(x);
    gn_apply<<<((long)NB * HW * CH / 4) / 256, 256>>>(x, gamma, beta);

    // 2) fused QKV: [16384,512] @ [512,1536] + bias, rounded
    gemm_tf32<false, true, false, true><<<dim3(QKVN / 128, (NB * HW) / 128, 1), 256>>>(
        hh, wqkvp, bqkvp, nullptr, qkv, CH, QKVN, QKVN, 0, 0, 0, CH, 1.0f);

    // 3) scores = scale * q @ k^T (per batch)
    gemm_tf32<true, false, false, false><<<dim3(HW / 128, HW / 128, NB), 256>>>(
        qkv, qkv + 512, nullptr, nullptr, sc, QKVN, QKVN, HW, sQ, sQ, sS, CH, scale);

    // 4) softmax
    softmax_rows<<<NB * HW, 256>>>(sc);

    // 5) attn @ v (per batch), rounded
    gemm_tf32<false, false, false, true><<<dim3(CH / 128, HW / 128, NB), 256>>>(
        sc, qkv + 1024, nullptr, nullptr, ao, HW, QKVN, CH, sS, sQ, sO, HW, 1.0f);

    // 6) proj + residual
    gemm_tf32<false, true, true, false><<<dim3(CH / 128, (NB * HW) / 128, 1), 256>>>(
        ao, wpr, bp, x, out, CH, CH, CH, 0, 0, 0, CH, 1.0f);
}

// round 11
// speedup vs baseline: 3.3961x; 2.8638x over previous
#include <cuda_runtime.h>
#include <cuda_bf16.h>
#include <mma.h>

using namespace nvcuda;

#define NB   4
#define HW   4096
#define CH   512
#define QKVN 1536
#define NGRP 32
#define CPG  16
#define GNEPS 1e-5f

// ---------------- scratch ----------------
__device__ __nv_bfloat16 g_h[(long)NB * HW * CH];
__device__ __nv_bfloat16 g_qkv[(long)NB * HW * QKVN];
__device__ __nv_bfloat16 g_p[(long)NB * HW * HW];      // bf16 probs, 128 MB
__device__ float         g_scores[(long)NB * HW * HW]; // fp32 logits, 256 MB
__device__ __nv_bfloat16 g_ao[(long)NB * HW * CH];
__device__ __nv_bfloat16 g_wqkv[CH * QKVN];
__device__ __nv_bfloat16 g_wpr[CH * CH];
__device__ float g_bqkv[QKVN];
__device__ float g_mean[NB * NGRP];
__device__ float g_rstd[NB * NGRP];

__device__ __forceinline__ void cpa16(void* s, const void* g) {
    unsigned sa = (unsigned)__cvta_generic_to_shared(s);
    asm volatile("cp.async.cg.shared.global [%0], [%1], 16;" :: "r"(sa), "l"(g));
}

// ---------------- weight prep: concat + bf16 ----------------
__global__ __launch_bounds__(256) void prep(const float* __restrict__ wq,
                                            const float* __restrict__ wk,
                                            const float* __restrict__ wv,
                                            const float* __restrict__ wp,
                                            const float* __restrict__ bq,
                                            const float* __restrict__ bk,
                                            const float* __restrict__ bv) {
    int idx = blockIdx.x * 256 + threadIdx.x;
    if (idx < CH * QKVN) {
        int c = idx / QKVN, col = idx - c * QKVN;
        int sel = col >> 9, cc = col & 511;
        const float* w = (sel == 0) ? wq : (sel == 1) ? wk : wv;
        g_wqkv[idx] = __float2bfloat16_rn(w[c * CH + cc]);
        if (idx < QKVN) {
            const float* bb = (idx < 512) ? bq : (idx < 1024) ? bk : bv;
            g_bqkv[idx] = bb[idx & 511];
        }
    } else {
        int j = idx - CH * QKVN;
        if (j < CH * CH) g_wpr[j] = __float2bfloat16_rn(wp[j]);
    }
}

// ---------------- GroupNorm stats ----------------
__global__ __launch_bounds__(256) void gn_stats(const float* __restrict__ x) {
    int bid = blockIdx.x;
    int b = bid >> 5, g = bid & 31;
    const float* base = x + (long)b * HW * CH + g * CPG;
    float s = 0.f, ss = 0.f;
    for (int p = threadIdx.x; p < HW; p += 256) {
        const float4* pp = (const float4*)(base + (long)p * CH);
#pragma unroll
        for (int i = 0; i < 4; i++) {
            float4 v = pp[i];
            s  += v.x + v.y + v.z + v.w;
            ss += v.x * v.x + v.y * v.y + v.z * v.z + v.w * v.w;
        }
    }
    __shared__ float sh[512];
    sh[threadIdx.x] = s; sh[256 + threadIdx.x] = ss;
    __syncthreads();
    for (int o = 128; o > 0; o >>= 1) {
        if (threadIdx.x < o) {
            sh[threadIdx.x] += sh[threadIdx.x + o];
            sh[256 + threadIdx.x] += sh[256 + threadIdx.x + o];
        }
        __syncthreads();
    }
    if (threadIdx.x == 0) {
        const float inv = 1.0f / (HW * CPG);
        float mean = sh[0] * inv;
        float var  = sh[256] * inv - mean * mean;
        g_mean[bid] = mean;
        g_rstd[bid] = rsqrtf(var + GNEPS);
    }
}

// ---------------- GroupNorm apply -> bf16 ----------------
__global__ __launch_bounds__(256) void gn_apply(const float* __restrict__ x,
                                                const float* __restrict__ gamma,
                                                const float* __restrict__ beta) {
    long i = (long)blockIdx.x * 256 + threadIdx.x;   // float4 index
    long i4 = i * 4;
    int b = (int)(i4 >> 21);
    int c = (int)(i4 & (CH - 1));
    int g = c >> 4;
    float mean = g_mean[b * NGRP + g];
    float rstd = g_rstd[b * NGRP + g];
    float4 v  = ((const float4*)x)[i];
    float4 ga = ((const float4*)gamma)[c >> 2];
    float4 be = ((const float4*)beta)[c >> 2];
    __nv_bfloat162 h0 = __floats2bfloat162_rn((v.x - mean) * rstd * ga.x + be.x,
                                              (v.y - mean) * rstd * ga.y + be.y);
    __nv_bfloat162 h1 = __floats2bfloat162_rn((v.z - mean) * rstd * ga.z + be.z,
                                              (v.w - mean) * rstd * ga.w + be.w);
    uint2 u; u.x = *(unsigned*)&h0; u.y = *(unsigned*)&h1;
    ((uint2*)g_h)[i] = u;
}

// ---------------- bf16 GEMM: 128x128x32 block, 8 warps, 64x32 warp tile -----
// C = alpha*A@op(B) (+bias) (+res).  BCOL: B is [N,K] row-major => C = A@B^T.
// OBF: output bf16, else fp32.
template<bool BCOL, bool BIAS, bool RES, bool OBF>
__global__ __launch_bounds__(256, 2)
void gemm_bf16(const __nv_bfloat16* __restrict__ A, const __nv_bfloat16* __restrict__ B,
               const float* __restrict__ bias, const float* __restrict__ res,
               void* __restrict__ Cv,
               int lda, int ldb, int ldc,
               long sA, long sB, long sC, int K, float alpha) {
    __shared__ __align__(16) __nv_bfloat16 As[2][128][40];   // 20 KB
    __shared__ __align__(16) __nv_bfloat16 Bs[2][128][40];   // !BCOL uses [2][32][136]

    const int bz = blockIdx.z;
    A += (long)bz * sA;  B += (long)bz * sB;
    const float* resp = RES ? (res + (long)bz * sC) : nullptr;

    const int bm = blockIdx.y * 128, bn = blockIdx.x * 128;
    const int tid = threadIdx.x, warp = tid >> 5, lane = tid & 31;
    const int wm = warp >> 2, wn = warp & 3;

    wmma::fragment<wmma::accumulator, 16, 16, 16, float> acc[4][2];
#pragma unroll
    for (int i = 0; i < 4; i++)
#pragma unroll
        for (int j = 0; j < 2; j++) wmma::fill_fragment(acc[i][j], 0.0f);

    auto stage = [&](int kt, int buf) {
        const int k0 = kt * 32;
#pragma unroll
        for (int r = 0; r < 2; r++) {
            int idx = tid + r * 256;
            int row = idx >> 2, c = (idx & 3) * 8;
            cpa16(&As[buf][row][c], A + (long)(bm + row) * lda + k0 + c);
        }
        if (BCOL) {
#pragma unroll
            for (int r = 0; r < 2; r++) {
                int idx = tid + r * 256;
                int row = idx >> 2, c = (idx & 3) * 8;
                cpa16(&Bs[buf][row][c], B + (long)(bn + row) * ldb + k0 + c);
            }
        } else {
            __nv_bfloat16* bsb = &Bs[buf][0][0];
#pragma unroll
            for (int r = 0; r < 2; r++) {
                int idx = tid + r * 256;
                int row = idx >> 4, c = (idx & 15) * 8;
                cpa16(bsb + row * 136 + c, B + (long)(k0 + row) * ldb + bn + c);
            }
        }
        asm volatile("cp.async.commit_group;" ::: "memory");
    };

    auto compute = [&](int buf) {
#pragma unroll
        for (int kk = 0; kk < 32; kk += 16) {
            wmma::fragment<wmma::matrix_a, 16, 16, 16, __nv_bfloat16, wmma::row_major> af[4];
#pragma unroll
            for (int i = 0; i < 4; i++)
                wmma::load_matrix_sync(af[i], &As[buf][wm * 64 + i * 16][kk], 40);
            if constexpr (BCOL) {
                wmma::fragment<wmma::matrix_b, 16, 16, 16, __nv_bfloat16, wmma::col_major> bf[2];
#pragma unroll
                for (int j = 0; j < 2; j++)
                    wmma::load_matrix_sync(bf[j], &Bs[buf][wn * 32 + j * 16][kk], 40);
#pragma unroll
                for (int i = 0; i < 4; i++)
#pragma unroll
                    for (int j = 0; j < 2; j++)
                        wmma::mma_sync(acc[i][j], af[i], bf[j], acc[i][j]);
            } else {
                const __nv_bfloat16* bsb = &Bs[buf][0][0];
                wmma::fragment<wmma::matrix_b, 16, 16, 16, __nv_bfloat16, wmma::row_major> bf[2];
#pragma unroll
                for (int j = 0; j < 2; j++)
                    wmma::load_matrix_sync(bf[j], bsb + kk * 136 + wn * 32 + j * 16, 136);
#pragma unroll
                for (int i = 0; i < 4; i++)
#pragma unroll
                    for (int j = 0; j < 2; j++)
                        wmma::mma_sync(acc[i][j], af[i], bf[j], acc[i][j]);
            }
        }
    };

    const int KT = K >> 5;
    stage(0, 0);
    for (int kt = 0; kt < KT; kt++) {
        const int buf = kt & 1;
        if (kt + 1 < KT) {
            stage(kt + 1, buf ^ 1);
            asm volatile("cp.async.wait_group 1;" ::: "memory");
        } else {
            asm volatile("cp.async.wait_group 0;" ::: "memory");
        }
        __syncthreads();
        compute(buf);
        __syncthreads();
    }

    // ---------------- epilogue ----------------
    float* ebuf = reinterpret_cast<float*>(&As[0][0][0]) + warp * 320;  // 16x20
    const int r = lane >> 1, cb = (lane & 1) * 8;
#pragma unroll
    for (int i = 0; i < 4; i++) {
#pragma unroll
        for (int j = 0; j < 2; j++) {
            wmma::store_matrix_sync(ebuf, acc[i][j], 20, wmma::mem_row_major);
            __syncwarp();
            float4 v0 = *(const float4*)(ebuf + r * 20 + cb);
            float4 v1 = *(const float4*)(ebuf + r * 20 + cb + 4);
            __syncwarp();
            const int gm = bm + wm * 64 + i * 16 + r;
            const int gnc = bn + wn * 32 + j * 16 + cb;
            float4 o0, o1;
            o0.x = v0.x * alpha; o0.y = v0.y * alpha; o0.z = v0.z * alpha; o0.w = v0.w * alpha;
            o1.x = v1.x * alpha; o1.y = v1.y * alpha; o1.z = v1.z * alpha; o1.w = v1.w * alpha;
            if (BIAS) {
                float4 b0 = *(const float4*)(bias + gnc);
                float4 b1 = *(const float4*)(bias + gnc + 4);
                o0.x += b0.x; o0.y += b0.y; o0.z += b0.z; o0.w += b0.w;
                o1.x += b1.x; o1.y += b1.y; o1.z += b1.z; o1.w += b1.w;
            }
            if (RES) {
                float4 r0 = *(const float4*)(resp + (long)gm * ldc + gnc);
                float4 r1 = *(const float4*)(resp + (long)gm * ldc + gnc + 4);
                o0.x += r0.x; o0.y += r0.y; o0.z += r0.z; o0.w += r0.w;
                o1.x += r1.x; o1.y += r1.y; o1.z += r1.z; o1.w += r1.w;
            }
            if (OBF) {
                __nv_bfloat16* cp = (__nv_bfloat16*)Cv + (long)bz * sC + (long)gm * ldc + gnc;
                __nv_bfloat162 pk[4] = {
                    __floats2bfloat162_rn(o0.x, o0.y), __floats2bfloat162_rn(o0.z, o0.w),
                    __floats2bfloat162_rn(o1.x, o1.y), __floats2bfloat162_rn(o1.z, o1.w)};
                *(uint4*)cp = *(const uint4*)pk;
            } else {
                float* cp = (float*)Cv + (long)bz * sC + (long)gm * ldc + gnc;
                *(float4*)cp = o0;
                *(float4*)(cp + 4) = o1;
            }
        }
    }
}

// ---------------- row softmax: fp32 logits -> bf16 probs ----------------
__global__ __launch_bounds__(256) void softmax_rows(const float* __restrict__ sc,
                                                    __nv_bfloat16* __restrict__ pr) {
    long row = blockIdx.x;
    const float* p = sc + row * (long)HW;
    __nv_bfloat16* pb = pr + row * (long)HW;
    int tid = threadIdx.x;
    float4 v[4];
    float mx = -1e30f;
#pragma unroll
    for (int i = 0; i < 4; i++) {
        v[i] = ((const float4*)p)[i * 256 + tid];
        mx = fmaxf(mx, fmaxf(fmaxf(v[i].x, v[i].y), fmaxf(v[i].z, v[i].w)));
    }
    __shared__ float sh[256];
    sh[tid] = mx; __syncthreads();
    for (int o = 128; o > 0; o >>= 1) {
        if (tid < o) sh[tid] = fmaxf(sh[tid], sh[tid + o]);
        __syncthreads();
    }
    mx = sh[0];
    __syncthreads();
    float s = 0.f;
#pragma unroll
    for (int i = 0; i < 4; i++) {
        v[i].x = __expf(v[i].x - mx); v[i].y = __expf(v[i].y - mx);
        v[i].z = __expf(v[i].z - mx); v[i].w = __expf(v[i].w - mx);
        s += v[i].x + v[i].y + v[i].z + v[i].w;
    }
    sh[tid] = s; __syncthreads();
    for (int o = 128; o > 0; o >>= 1) {
        if (tid < o) sh[tid] += sh[tid + o];
        __syncthreads();
    }
    float inv = 1.0f / sh[0];
#pragma unroll
    for (int i = 0; i < 4; i++) {
        __nv_bfloat162 h0 = __floats2bfloat162_rn(v[i].x * inv, v[i].y * inv);
        __nv_bfloat162 h1 = __floats2bfloat162_rn(v[i].z * inv, v[i].w * inv);
        uint2 u; u.x = *(unsigned*)&h0; u.y = *(unsigned*)&h1;
        ((uint2*)pb)[i * 256 + tid] = u;
    }
}

// ---------------- launch ----------------
extern "C" void kernel_launch(void* const* d_in, const int* in_sizes, int n_in,
                              void* d_out, int out_size) {
    const float* x     = (const float*)d_in[0];
    const float* gamma = (const float*)d_in[1];
    const float* beta  = (const float*)d_in[2];
    const float* wq = (const float*)d_in[3];
    const float* bq = (const float*)d_in[4];
    const float* wk = (const float*)d_in[5];
    const float* bk = (const float*)d_in[6];
    const float* wv = (const float*)d_in[7];
    const float* bv = (const float*)d_in[8];
    const float* wp = (const float*)d_in[9];
    const float* bp = (const float*)d_in[10];
    float* out = (float*)d_out;

    __nv_bfloat16 *hh, *qkv, *ao, *pr, *wqkvp, *wpr;
    float *sc, *bqkvp;
    cudaGetSymbolAddress((void**)&hh, g_h);
    cudaGetSymbolAddress((void**)&qkv, g_qkv);
    cudaGetSymbolAddress((void**)&ao, g_ao);
    cudaGetSymbolAddress((void**)&pr, g_p);
    cudaGetSymbolAddress((void**)&sc, g_scores);
    cudaGetSymbolAddress((void**)&wqkvp, g_wqkv);
    cudaGetSymbolAddress((void**)&bqkvp, g_bqkv);
    cudaGetSymbolAddress((void**)&wpr, g_wpr);

    const long sQ = (long)HW * QKVN;
    const long sS = (long)HW * HW;
    const long sO = (long)HW * CH;
    const float scale = 0.044194173824159216f;   // 1/sqrt(512)

    prep<<<(CH * QKVN + CH * CH) / 256, 256>>>(wq, wk, wv, wp, bq, bk, bv);

    gn_stats<<<NB * NGRP, 256>>>(x);
    gn_apply<<<(int)(((long)NB * HW * CH / 4) / 256), 256>>>(x, gamma, beta);

    // fused QKV: [16384,512] @ [512,1536] + bias -> bf16
    gemm_bf16<false, true, false, true><<<dim3(QKVN / 128, (NB * HW) / 128, 1), 256>>>(
        hh, wqkvp, bqkvp, nullptr, qkv, CH, QKVN, QKVN, 0, 0, 0, CH, 1.0f);

    // scores = scale * q @ k^T -> fp32
    gemm_bf16<true, false, false, false><<<dim3(HW / 128, HW / 128, NB), 256>>>(
        qkv, qkv + 512, nullptr, nullptr, sc, QKVN, QKVN, HW, sQ, sQ, sS, CH, scale);

    softmax_rows<<<NB * HW, 256>>>(sc, pr);

    // attn @ v -> bf16
    gemm_bf16<false, false, false, true><<<dim3(CH / 128, HW / 128, NB), 256>>>(
        pr, qkv + 1024, nullptr, nullptr, ao, HW, QKVN, CH, sS, sQ, sO, HW, 1.0f);

    // proj + residual -> fp32 out
    gemm_bf16<false, true, true, false><<<dim3(CH / 128, (NB * HW) / 128, 1), 256>>>(
        ao, wpr, bp, x, out, CH, CH, CH, 0, 0, 0, CH, 1.0f);
}

// round 13
// speedup vs baseline: 3.5515x; 1.0457x over previous
#include <cuda_runtime.h>
#include <cuda_bf16.h>
#include <mma.h>

using namespace nvcuda;

#define NB   4
#define HW   4096
#define CH   512
#define QKVN 1536
#define NGRP 32
#define CPG  16
#define GNEPS 1e-5f

#define BM 128
#define BN 256
#define BK 64

// ---------------- scratch ----------------
__device__ __nv_bfloat16 g_h[(long)NB * HW * CH];
__device__ __nv_bfloat16 g_qkv[(long)NB * HW * QKVN];
__device__ __nv_bfloat16 g_p[(long)NB * HW * HW];      // bf16 probs
__device__ float         g_scores[(long)NB * HW * HW]; // fp32 logits
__device__ __nv_bfloat16 g_ao[(long)NB * HW * CH];
__device__ __nv_bfloat16 g_wqkv[CH * QKVN];            // [k][n] concat
__device__ __nv_bfloat16 g_wpr[CH * CH];               // [k][n]
__device__ float g_bqkv[QKVN];
__device__ float g_mean[NB * NGRP];
__device__ float g_rstd[NB * NGRP];

__device__ __forceinline__ void cpa16(void* s, const void* g) {
    unsigned sa = (unsigned)__cvta_generic_to_shared(s);
    asm volatile("cp.async.cg.shared.global [%0], [%1], 16;" :: "r"(sa), "l"(g));
}

// ---------------- weight prep: concat + bf16 (row-major [K][N]) -------------
__global__ __launch_bounds__(256) void prep(const float* __restrict__ wq,
                                            const float* __restrict__ wk,
                                            const float* __restrict__ wv,
                                            const float* __restrict__ wp,
                                            const float* __restrict__ bq,
                                            const float* __restrict__ bk,
                                            const float* __restrict__ bv) {
    int idx = blockIdx.x * 256 + threadIdx.x;
    if (idx < CH * QKVN) {
        int c = idx / QKVN, col = idx - c * QKVN;
        int sel = col >> 9, cc = col & 511;
        const float* w = (sel == 0) ? wq : (sel == 1) ? wk : wv;
        g_wqkv[idx] = __float2bfloat16_rn(w[c * CH + cc]);
        if (idx < QKVN) {
            const float* bb = (idx < 512) ? bq : (idx < 1024) ? bk : bv;
            g_bqkv[idx] = bb[idx & 511];
        }
    } else {
        int j = idx - CH * QKVN;
        if (j < CH * CH) g_wpr[j] = __float2bfloat16_rn(wp[j]);
    }
}

// ---------------- GroupNorm stats ----------------
__global__ __launch_bounds__(256) void gn_stats(const float* __restrict__ x) {
    int bid = blockIdx.x;
    int b = bid >> 5, g = bid & 31;
    const float* base = x + (long)b * HW * CH + g * CPG;
    float s = 0.f, ss = 0.f;
    for (int p = threadIdx.x; p < HW; p += 256) {
        const float4* pp = (const float4*)(base + (long)p * CH);
#pragma unroll
        for (int i = 0; i < 4; i++) {
            float4 v = pp[i];
            s  += v.x + v.y + v.z + v.w;
            ss += v.x * v.x + v.y * v.y + v.z * v.z + v.w * v.w;
        }
    }
    __shared__ float sh[512];
    sh[threadIdx.x] = s; sh[256 + threadIdx.x] = ss;
    __syncthreads();
    for (int o = 128; o > 0; o >>= 1) {
        if (threadIdx.x < o) {
            sh[threadIdx.x] += sh[threadIdx.x + o];
            sh[256 + threadIdx.x] += sh[256 + threadIdx.x + o];
        }
        __syncthreads();
    }
    if (threadIdx.x == 0) {
        const float inv = 1.0f / (HW * CPG);
        float mean = sh[0] * inv;
        float var  = sh[256] * inv - mean * mean;
        g_mean[bid] = mean;
        g_rstd[bid] = rsqrtf(var + GNEPS);
    }
}

// ---------------- GroupNorm apply -> bf16 ----------------
__global__ __launch_bounds__(256) void gn_apply(const float* __restrict__ x,
                                                const float* __restrict__ gamma,
                                                const float* __restrict__ beta) {
    long i = (long)blockIdx.x * 256 + threadIdx.x;
    long i4 = i * 4;
    int b = (int)(i4 >> 21);
    int c = (int)(i4 & (CH - 1));
    int g = c >> 4;
    float mean = g_mean[b * NGRP + g];
    float rstd = g_rstd[b * NGRP + g];
    float4 v  = ((const float4*)x)[i];
    float4 ga = ((const float4*)gamma)[c >> 2];
    float4 be = ((const float4*)beta)[c >> 2];
    __nv_bfloat162 h0 = __floats2bfloat162_rn((v.x - mean) * rstd * ga.x + be.x,
                                              (v.y - mean) * rstd * ga.y + be.y);
    __nv_bfloat162 h1 = __floats2bfloat162_rn((v.z - mean) * rstd * ga.z + be.z,
                                              (v.w - mean) * rstd * ga.w + be.w);
    uint2 u; u.x = *(unsigned*)&h0; u.y = *(unsigned*)&h1;
    ((uint2*)g_h)[i] = u;
}

// ---------------- bf16 GEMM: 128x256x64, 8 warps, 64x64 warp tile -----------
// C = alpha*A@op(B) (+bias)(+res). BCOL: B [N,K] row-major => C = A@B^T.
// smem layout (dynamic): As [2][128][72] bf16 at 0 (36864 B)
//                        Bs at 36864: BCOL [2][256][72] (73728 B)
//                                     else [2][64][264] (67584 B)
#define SMEM_B_OFF 36864
#define SMEMSZ (36864 + 73728)

template<bool BCOL, bool BIAS, bool RES, bool OBF>
__global__ __launch_bounds__(256)
void gemm_bf16(const __nv_bfloat16* __restrict__ A, const __nv_bfloat16* __restrict__ B,
               const float* __restrict__ bias, const float* __restrict__ res,
               void* __restrict__ Cv,
               int lda, int ldb, int ldc,
               long sA, long sB, long sC, int K, float alpha) {
    extern __shared__ __align__(16) char smem[];
    __nv_bfloat16* Asb = (__nv_bfloat16*)smem;
    __nv_bfloat16* Bsb = (__nv_bfloat16*)(smem + SMEM_B_OFF);

    const int bz = blockIdx.z;
    A += (long)bz * sA;  B += (long)bz * sB;
    const float* resp = RES ? (res + (long)bz * sC) : nullptr;

    const int bm = blockIdx.y * BM, bn = blockIdx.x * BN;
    const int tid = threadIdx.x, warp = tid >> 5, lane = tid & 31;
    const int wm = warp >> 2, wn = warp & 3;          // 2 x 4 warp grid

    wmma::fragment<wmma::accumulator, 16, 16, 16, float> acc[4][4];
#pragma unroll
    for (int i = 0; i < 4; i++)
#pragma unroll
        for (int j = 0; j < 4; j++) wmma::fill_fragment(acc[i][j], 0.0f);

    auto stage = [&](int kt, int buf) {
        const int k0 = kt * BK;
        __nv_bfloat16* As = Asb + buf * (128 * 72);
#pragma unroll
        for (int r = 0; r < 4; r++) {                 // A: 128 x 64
            int idx = tid + r * 256;
            int row = idx >> 3, c = (idx & 7) * 8;
            cpa16(As + row * 72 + c, A + (long)(bm + row) * lda + k0 + c);
        }
        if (BCOL) {
            __nv_bfloat16* Bs = Bsb + buf * (256 * 72);
#pragma unroll
            for (int r = 0; r < 8; r++) {             // B: 256 x 64
                int idx = tid + r * 256;
                int row = idx >> 3, c = (idx & 7) * 8;
                cpa16(Bs + row * 72 + c, B + (long)(bn + row) * ldb + k0 + c);
            }
        } else {
            __nv_bfloat16* Bs = Bsb + buf * (64 * 264);
#pragma unroll
            for (int r = 0; r < 8; r++) {             // B: 64 x 256
                int idx = tid + r * 256;
                int row = idx >> 5, c = (idx & 31) * 8;
                cpa16(Bs + row * 264 + c, B + (long)(k0 + row) * ldb + bn + c);
            }
        }
        asm volatile("cp.async.commit_group;" ::: "memory");
    };

    auto compute = [&](int buf) {
        const __nv_bfloat16* As = Asb + buf * (128 * 72);
#pragma unroll
        for (int kk = 0; kk < BK; kk += 16) {
            wmma::fragment<wmma::matrix_a, 16, 16, 16, __nv_bfloat16, wmma::row_major> af[4];
#pragma unroll
            for (int i = 0; i < 4; i++)
                wmma::load_matrix_sync(af[i], As + (wm * 64 + i * 16) * 72 + kk, 72);
            if constexpr (BCOL) {
                const __nv_bfloat16* Bs = Bsb + buf * (256 * 72);
                wmma::fragment<wmma::matrix_b, 16, 16, 16, __nv_bfloat16, wmma::col_major> bf[4];
#pragma unroll
                for (int j = 0; j < 4; j++)
                    wmma::load_matrix_sync(bf[j], Bs + (wn * 64 + j * 16) * 72 + kk, 72);
#pragma unroll
                for (int i = 0; i < 4; i++)
#pragma unroll
                    for (int j = 0; j < 4; j++)
                        wmma::mma_sync(acc[i][j], af[i], bf[j], acc[i][j]);
            } else {
                const __nv_bfloat16* Bs = Bsb + buf * (64 * 264);
                wmma::fragment<wmma::matrix_b, 16, 16, 16, __nv_bfloat16, wmma::row_major> bf[4];
#pragma unroll
                for (int j = 0; j < 4; j++)
                    wmma::load_matrix_sync(bf[j], Bs + kk * 264 + wn * 64 + j * 16, 264);
#pragma unroll
                for (int i = 0; i < 4; i++)
#pragma unroll
                    for (int j = 0; j < 4; j++)
                        wmma::mma_sync(acc[i][j], af[i], bf[j], acc[i][j]);
            }
        }
    };

    const int KT = K / BK;
    stage(0, 0);
    for (int kt = 0; kt < KT; kt++) {
        const int buf = kt & 1;
        if (kt + 1 < KT) {
            stage(kt + 1, buf ^ 1);
            asm volatile("cp.async.wait_group 1;" ::: "memory");
        } else {
            asm volatile("cp.async.wait_group 0;" ::: "memory");
        }
        __syncthreads();
        compute(buf);
        __syncthreads();
    }

    // ---------------- epilogue ----------------
    if (!BIAS && !RES && !OBF) {
        // direct fragment store (scores): alpha in registers
        float* Cp = (float*)Cv + (long)bz * sC;
#pragma unroll
        for (int i = 0; i < 4; i++)
#pragma unroll
            for (int j = 0; j < 4; j++) {
#pragma unroll
                for (int t = 0; t < acc[i][j].num_elements; t++) acc[i][j].x[t] *= alpha;
                wmma::store_matrix_sync(
                    Cp + (long)(bm + wm * 64 + i * 16) * ldc + bn + wn * 64 + j * 16,
                    acc[i][j], ldc, wmma::mem_row_major);
            }
    } else {
        float* ebuf = (float*)smem + warp * 320;      // 16x20 per warp
        const int r = lane >> 1, cb = (lane & 1) * 8;
#pragma unroll
        for (int i = 0; i < 4; i++) {
#pragma unroll
            for (int j = 0; j < 4; j++) {
                wmma::store_matrix_sync(ebuf, acc[i][j], 20, wmma::mem_row_major);
                __syncwarp();
                float4 v0 = *(const float4*)(ebuf + r * 20 + cb);
                float4 v1 = *(const float4*)(ebuf + r * 20 + cb + 4);
                __syncwarp();
                const int gm = bm + wm * 64 + i * 16 + r;
                const int gnc = bn + wn * 64 + j * 16 + cb;
                float o[8] = {v0.x * alpha, v0.y * alpha, v0.z * alpha, v0.w * alpha,
                              v1.x * alpha, v1.y * alpha, v1.z * alpha, v1.w * alpha};
                if (BIAS) {
                    float4 b0 = *(const float4*)(bias + gnc);
                    float4 b1 = *(const float4*)(bias + gnc + 4);
                    o[0] += b0.x; o[1] += b0.y; o[2] += b0.z; o[3] += b0.w;
                    o[4] += b1.x; o[5] += b1.y; o[6] += b1.z; o[7] += b1.w;
                }
                if (RES) {
                    const float* rp = resp + (long)gm * ldc + gnc;
                    float4 r0 = *(const float4*)rp;
                    float4 r1 = *(const float4*)(rp + 4);
                    o[0] += r0.x; o[1] += r0.y; o[2] += r0.z; o[3] += r0.w;
                    o[4] += r1.x; o[5] += r1.y; o[6] += r1.z; o[7] += r1.w;
                }
                if (OBF) {
                    __nv_bfloat16* cp = (__nv_bfloat16*)Cv + (long)bz * sC + (long)gm * ldc + gnc;
                    __nv_bfloat162 p0 = __floats2bfloat162_rn(o[0], o[1]);
                    __nv_bfloat162 p1 = __floats2bfloat162_rn(o[2], o[3]);
                    __nv_bfloat162 p2 = __floats2bfloat162_rn(o[4], o[5]);
                    __nv_bfloat162 p3 = __floats2bfloat162_rn(o[6], o[7]);
                    uint4 u;
                    u.x = *(unsigned*)&p0; u.y = *(unsigned*)&p1;
                    u.z = *(unsigned*)&p2; u.w = *(unsigned*)&p3;
                    *(uint4*)cp = u;
                } else {
                    float* cp = (float*)Cv + (long)bz * sC + (long)gm * ldc + gnc;
                    *(float4*)cp       = make_float4(o[0], o[1], o[2], o[3]);
                    *(float4*)(cp + 4) = make_float4(o[4], o[5], o[6], o[7]);
                }
            }
        }
    }
}

// ---------------- row softmax: fp32 logits -> bf16 probs ----------------
__global__ __launch_bounds__(256) void softmax_rows(const float* __restrict__ sc,
                                                    __nv_bfloat16* __restrict__ pr) {
    long row = blockIdx.x;
    const float* p = sc + row * (long)HW;
    __nv_bfloat16* pb = pr + row * (long)HW;
    int tid = threadIdx.x;
    float4 v[4];
    float mx = -1e30f;
#pragma unroll
    for (int i = 0; i < 4; i++) {
        v[i] = ((const float4*)p)[i * 256 + tid];
        mx = fmaxf(mx, fmaxf(fmaxf(v[i].x, v[i].y), fmaxf(v[i].z, v[i].w)));
    }
    __shared__ float sh[256];
    sh[tid] = mx; __syncthreads();
    for (int o = 128; o > 0; o >>= 1) {
        if (tid < o) sh[tid] = fmaxf(sh[tid], sh[tid + o]);
        __syncthreads();
    }
    mx = sh[0];
    __syncthreads();
    float s = 0.f;
#pragma unroll
    for (int i = 0; i < 4; i++) {
        v[i].x = __expf(v[i].x - mx); v[i].y = __expf(v[i].y - mx);
        v[i].z = __expf(v[i].z - mx); v[i].w = __expf(v[i].w - mx);
        s += v[i].x + v[i].y + v[i].z + v[i].w;
    }
    sh[tid] = s; __syncthreads();
    for (int o = 128; o > 0; o >>= 1) {
        if (tid < o) sh[tid] += sh[tid + o];
        __syncthreads();
    }
    float inv = 1.0f / sh[0];
#pragma unroll
    for (int i = 0; i < 4; i++) {
        __nv_bfloat162 h0 = __floats2bfloat162_rn(v[i].x * inv, v[i].y * inv);
        __nv_bfloat162 h1 = __floats2bfloat162_rn(v[i].z * inv, v[i].w * inv);
        uint2 u; u.x = *(unsigned*)&h0; u.y = *(unsigned*)&h1;
        ((uint2*)pb)[i * 256 + tid] = u;
    }
}

// ---------------- launch ----------------
extern "C" void kernel_launch(void* const* d_in, const int* in_sizes, int n_in,
                              void* d_out, int out_size) {
    const float* x     = (const float*)d_in[0];
    const float* gamma = (const float*)d_in[1];
    const float* beta  = (const float*)d_in[2];
    const float* wq = (const float*)d_in[3];
    const float* bq = (const float*)d_in[4];
    const float* wk = (const float*)d_in[5];
    const float* bk = (const float*)d_in[6];
    const float* wv = (const float*)d_in[7];
    const float* bv = (const float*)d_in[8];
    const float* wp = (const float*)d_in[9];
    const float* bp = (const float*)d_in[10];
    float* out = (float*)d_out;

    __nv_bfloat16 *hh, *qkv, *ao, *pr, *wqkvp, *wpr;
    float *sc, *bqkvp;
    cudaGetSymbolAddress((void**)&hh, g_h);
    cudaGetSymbolAddress((void**)&qkv, g_qkv);
    cudaGetSymbolAddress((void**)&ao, g_ao);
    cudaGetSymbolAddress((void**)&pr, g_p);
    cudaGetSymbolAddress((void**)&sc, g_scores);
    cudaGetSymbolAddress((void**)&wqkvp, g_wqkv);
    cudaGetSymbolAddress((void**)&bqkvp, g_bqkv);
    cudaGetSymbolAddress((void**)&wpr, g_wpr);

    cudaFuncSetAttribute(gemm_bf16<false, true,  false, true >, cudaFuncAttributeMaxDynamicSharedMemorySize, SMEMSZ);
    cudaFuncSetAttribute(gemm_bf16<true,  false, false, false>, cudaFuncAttributeMaxDynamicSharedMemorySize, SMEMSZ);
    cudaFuncSetAttribute(gemm_bf16<false, false, false, true >, cudaFuncAttributeMaxDynamicSharedMemorySize, SMEMSZ);
    cudaFuncSetAttribute(gemm_bf16<false, true,  true,  false>, cudaFuncAttributeMaxDynamicSharedMemorySize, SMEMSZ);

    const long sQ = (long)HW * QKVN;
    const long sS = (long)HW * HW;
    const long sO = (long)HW * CH;
    const float scale = 0.044194173824159216f;   // 1/sqrt(512)

    prep<<<(CH * QKVN + CH * CH) / 256, 256>>>(wq, wk, wv, wp, bq, bk, bv);

    gn_stats<<<NB * NGRP, 256>>>(x);
    gn_apply<<<(int)(((long)NB * HW * CH / 4) / 256), 256>>>(x, gamma, beta);

    // fused QKV: [16384,512] @ [512,1536] + bias -> bf16
    gemm_bf16<false, true, false, true><<<dim3(QKVN / BN, (NB * HW) / BM, 1), 256, SMEMSZ>>>(
        hh, wqkvp, bqkvp, nullptr, qkv, CH, QKVN, QKVN, 0, 0, 0, CH, 1.0f);

    // scores = scale * q @ k^T -> fp32 (direct fragment store)
    gemm_bf16<true, false, false, false><<<dim3(HW / BN, HW / BM, NB), 256, SMEMSZ>>>(
        qkv, qkv + 512, nullptr, nullptr, sc, QKVN, QKVN, HW, sQ, sQ, sS, CH, scale);

    softmax_rows<<<NB * HW, 256>>>(sc, pr);

    // attn @ v -> bf16
    gemm_bf16<false, false, false, true><<<dim3(CH / BN, HW / BM, NB), 256, SMEMSZ>>>(
        pr, qkv + 1024, nullptr, nullptr, ao, HW, QKVN, CH, sS, sQ, sO, HW, 1.0f);

    // proj + residual -> fp32 out
    gemm_bf16<false, true, true, false><<<dim3(CH / BN, (NB * HW) / BM, 1), 256, SMEMSZ>>>(
        ao, wpr, bp, x, out, CH, CH, CH, 0, 0, 0, CH, 1.0f);
}

// round 15
// speedup vs baseline: 3.7374x; 1.0524x over previous
#include <cuda_runtime.h>
#include <cuda_bf16.h>
#include <mma.h>

using namespace nvcuda;

#define NB   4
#define HW   4096
#define CH   512
#define QKVN 1536
#define NGRP 32
#define CPG  16
#define GNEPS 1e-5f

#define BM 128
#define BN 256
#define BK 64

// ---------------- scratch ----------------
__device__ __nv_bfloat16 g_h[(long)NB * HW * CH];
__device__ __nv_bfloat16 g_qkv[(long)NB * HW * QKVN];
__device__ __nv_bfloat16 g_p[(long)NB * HW * HW];      // bf16 unnormalized probs
__device__ float         g_psum[(long)NB * 64 * HW];   // per-64col-tile row partials
__device__ float         g_rowsum[NB * HW];
__device__ __nv_bfloat16 g_ao[(long)NB * HW * CH];
__device__ __nv_bfloat16 g_wqkv[CH * QKVN];            // [k][n] concat
__device__ __nv_bfloat16 g_wpr[CH * CH];               // [k][n]
__device__ float g_bqkv[QKVN];
__device__ float g_mean[NB * NGRP];
__device__ float g_rstd[NB * NGRP];

__device__ __forceinline__ void cpa16(void* s, const void* g) {
    unsigned sa = (unsigned)__cvta_generic_to_shared(s);
    asm volatile("cp.async.cg.shared.global [%0], [%1], 16;" :: "r"(sa), "l"(g));
}

// ---------------- weight prep: concat + bf16 (row-major [K][N]) -------------
__global__ __launch_bounds__(256) void prep(const float* __restrict__ wq,
                                            const float* __restrict__ wk,
                                            const float* __restrict__ wv,
                                            const float* __restrict__ wp,
                                            const float* __restrict__ bq,
                                            const float* __restrict__ bk,
                                            const float* __restrict__ bv) {
    int idx = blockIdx.x * 256 + threadIdx.x;
    if (idx < CH * QKVN) {
        int c = idx / QKVN, col = idx - c * QKVN;
        int sel = col >> 9, cc = col & 511;
        const float* w = (sel == 0) ? wq : (sel == 1) ? wk : wv;
        g_wqkv[idx] = __float2bfloat16_rn(w[c * CH + cc]);
        if (idx < QKVN) {
            const float* bb = (idx < 512) ? bq : (idx < 1024) ? bk : bv;
            g_bqkv[idx] = bb[idx & 511];
        }
    } else {
        int j = idx - CH * QKVN;
        if (j < CH * CH) g_wpr[j] = __float2bfloat16_rn(wp[j]);
    }
}

// ---------------- GroupNorm stats ----------------
__global__ __launch_bounds__(256) void gn_stats(const float* __restrict__ x) {
    int bid = blockIdx.x;
    int b = bid >> 5, g = bid & 31;
    const float* base = x + (long)b * HW * CH + g * CPG;
    float s = 0.f, ss = 0.f;
    for (int p = threadIdx.x; p < HW; p += 256) {
        const float4* pp = (const float4*)(base + (long)p * CH);
#pragma unroll
        for (int i = 0; i < 4; i++) {
            float4 v = pp[i];
            s  += v.x + v.y + v.z + v.w;
            ss += v.x * v.x + v.y * v.y + v.z * v.z + v.w * v.w;
        }
    }
    __shared__ float sh[512];
    sh[threadIdx.x] = s; sh[256 + threadIdx.x] = ss;
    __syncthreads();
    for (int o = 128; o > 0; o >>= 1) {
        if (threadIdx.x < o) {
            sh[threadIdx.x] += sh[threadIdx.x + o];
            sh[256 + threadIdx.x] += sh[256 + threadIdx.x + o];
        }
        __syncthreads();
    }
    if (threadIdx.x == 0) {
        const float inv = 1.0f / (HW * CPG);
        float mean = sh[0] * inv;
        float var  = sh[256] * inv - mean * mean;
        g_mean[bid] = mean;
        g_rstd[bid] = rsqrtf(var + GNEPS);
    }
}

// ---------------- GroupNorm apply -> bf16 ----------------
__global__ __launch_bounds__(256) void gn_apply(const float* __restrict__ x,
                                                const float* __restrict__ gamma,
                                                const float* __restrict__ beta) {
    long i = (long)blockIdx.x * 256 + threadIdx.x;
    long i4 = i * 4;
    int b = (int)(i4 >> 21);
    int c = (int)(i4 & (CH - 1));
    int g = c >> 4;
    float mean = g_mean[b * NGRP + g];
    float rstd = g_rstd[b * NGRP + g];
    float4 v  = ((const float4*)x)[i];
    float4 ga = ((const float4*)gamma)[c >> 2];
    float4 be = ((const float4*)beta)[c >> 2];
    __nv_bfloat162 h0 = __floats2bfloat162_rn((v.x - mean) * rstd * ga.x + be.x,
                                              (v.y - mean) * rstd * ga.y + be.y);
    __nv_bfloat162 h1 = __floats2bfloat162_rn((v.z - mean) * rstd * ga.z + be.z,
                                              (v.w - mean) * rstd * ga.w + be.w);
    uint2 u; u.x = *(unsigned*)&h0; u.y = *(unsigned*)&h1;
    ((uint2*)g_h)[i] = u;
}

// ---------------- rowsum reduce: 64 partials per row ----------------
__global__ __launch_bounds__(256) void rowsum_reduce() {
    int gid = blockIdx.x * 256 + threadIdx.x;       // NB*HW threads
    int b = gid >> 12, row = gid & (HW - 1);
    const float* p = g_psum + (long)b * 64 * HW + row;
    float s = 0.f;
#pragma unroll
    for (int t = 0; t < 64; t++) s += p[(long)t * HW];
    g_rowsum[gid] = s;
}

// ---------------- bf16 GEMM: 128x256x64, 8 warps, 64x64 warp tile -----------
// C = alpha*A@op(B) (+bias)(+res). BCOL: B [N,K] row-major => C = A@B^T.
// EXPP: out = exp(alpha*acc) -> bf16, emit row-sum partials to aux.
// RSUM: out *= 1/aux[row] (rowsum divide).
#define SMEM_B_OFF 36864
#define SMEMSZ (36864 + 73728)

template<bool BCOL, bool BIAS, bool RES, bool OBF, bool EXPP, bool RSUM>
__global__ __launch_bounds__(256)
void gemm_bf16(const __nv_bfloat16* __restrict__ A, const __nv_bfloat16* __restrict__ B,
               const float* __restrict__ bias, const float* __restrict__ res,
               float* __restrict__ aux,
               void* __restrict__ Cv,
               int lda, int ldb, int ldc,
               long sA, long sB, long sC, int K, float alpha) {
    extern __shared__ __align__(16) char smem[];
    __nv_bfloat16* Asb = (__nv_bfloat16*)smem;
    __nv_bfloat16* Bsb = (__nv_bfloat16*)(smem + SMEM_B_OFF);

    const int bz = blockIdx.z;
    A += (long)bz * sA;  B += (long)bz * sB;
    const float* resp = RES ? (res + (long)bz * sC) : nullptr;

    const int bm = blockIdx.y * BM, bn = blockIdx.x * BN;
    const int tid = threadIdx.x, warp = tid >> 5, lane = tid & 31;
    const int wm = warp >> 2, wn = warp & 3;          // 2 x 4 warp grid

    wmma::fragment<wmma::accumulator, 16, 16, 16, float> acc[4][4];
#pragma unroll
    for (int i = 0; i < 4; i++)
#pragma unroll
        for (int j = 0; j < 4; j++) wmma::fill_fragment(acc[i][j], 0.0f);

    auto stage = [&](int kt, int buf) {
        const int k0 = kt * BK;
        __nv_bfloat16* As = Asb + buf * (128 * 72);
#pragma unroll
        for (int r = 0; r < 4; r++) {                 // A: 128 x 64
            int idx = tid + r * 256;
            int row = idx >> 3, c = (idx & 7) * 8;
            cpa16(As + row * 72 + c, A + (long)(bm + row) * lda + k0 + c);
        }
        if (BCOL) {
            __nv_bfloat16* Bs = Bsb + buf * (256 * 72);
#pragma unroll
            for (int r = 0; r < 8; r++) {             // B: 256 x 64
                int idx = tid + r * 256;
                int row = idx >> 3, c = (idx & 7) * 8;
                cpa16(Bs + row * 72 + c, B + (long)(bn + row) * ldb + k0 + c);
            }
        } else {
            __nv_bfloat16* Bs = Bsb + buf * (64 * 264);
#pragma unroll
            for (int r = 0; r < 8; r++) {             // B: 64 x 256
                int idx = tid + r * 256;
                int row = idx >> 5, c = (idx & 31) * 8;
                cpa16(Bs + row * 264 + c, B + (long)(k0 + row) * ldb + bn + c);
            }
        }
        asm volatile("cp.async.commit_group;" ::: "memory");
    };

    auto compute = [&](int buf) {
        const __nv_bfloat16* As = Asb + buf * (128 * 72);
#pragma unroll
        for (int kk = 0; kk < BK; kk += 16) {
            wmma::fragment<wmma::matrix_a, 16, 16, 16, __nv_bfloat16, wmma::row_major> af[4];
#pragma unroll
            for (int i = 0; i < 4; i++)
                wmma::load_matrix_sync(af[i], As + (wm * 64 + i * 16) * 72 + kk, 72);
            if constexpr (BCOL) {
                const __nv_bfloat16* Bs = Bsb + buf * (256 * 72);
                wmma::fragment<wmma::matrix_b, 16, 16, 16, __nv_bfloat16, wmma::col_major> bf[4];
#pragma unroll
                for (int j = 0; j < 4; j++)
                    wmma::load_matrix_sync(bf[j], Bs + (wn * 64 + j * 16) * 72 + kk, 72);
#pragma unroll
                for (int i = 0; i < 4; i++)
#pragma unroll
                    for (int j = 0; j < 4; j++)
                        wmma::mma_sync(acc[i][j], af[i], bf[j], acc[i][j]);
            } else {
                const __nv_bfloat16* Bs = Bsb + buf * (64 * 264);
                wmma::fragment<wmma::matrix_b, 16, 16, 16, __nv_bfloat16, wmma::row_major> bf[4];
#pragma unroll
                for (int j = 0; j < 4; j++)
                    wmma::load_matrix_sync(bf[j], Bs + kk * 264 + wn * 64 + j * 16, 264);
#pragma unroll
                for (int i = 0; i < 4; i++)
#pragma unroll
                    for (int j = 0; j < 4; j++)
                        wmma::mma_sync(acc[i][j], af[i], bf[j], acc[i][j]);
            }
        }
    };

    const int KT = K / BK;
    stage(0, 0);
    for (int kt = 0; kt < KT; kt++) {
        const int buf = kt & 1;
        if (kt + 1 < KT) {
            stage(kt + 1, buf ^ 1);
            asm volatile("cp.async.wait_group 1;" ::: "memory");
        } else {
            asm volatile("cp.async.wait_group 0;" ::: "memory");
        }
        __syncthreads();
        compute(buf);
        __syncthreads();
    }

    // ---------------- epilogue (staged per-fragment) ----------------
    float* ebuf = (float*)smem + warp * 320;          // 16x20 per warp
    const int r = lane >> 1, cb = (lane & 1) * 8;
#pragma unroll
    for (int i = 0; i < 4; i++) {
        float rs = 0.f;                               // EXPP row partial (this thread)
        const int gm = bm + wm * 64 + i * 16 + r;
#pragma unroll
        for (int j = 0; j < 4; j++) {
            wmma::store_matrix_sync(ebuf, acc[i][j], 20, wmma::mem_row_major);
            __syncwarp();
            float4 v0 = *(const float4*)(ebuf + r * 20 + cb);
            float4 v1 = *(const float4*)(ebuf + r * 20 + cb + 4);
            __syncwarp();
            const int gnc = bn + wn * 64 + j * 16 + cb;
            float o[8] = {v0.x * alpha, v0.y * alpha, v0.z * alpha, v0.w * alpha,
                          v1.x * alpha, v1.y * alpha, v1.z * alpha, v1.w * alpha};
            if (BIAS) {
                float4 b0 = *(const float4*)(bias + gnc);
                float4 b1 = *(const float4*)(bias + gnc + 4);
                o[0] += b0.x; o[1] += b0.y; o[2] += b0.z; o[3] += b0.w;
                o[4] += b1.x; o[5] += b1.y; o[6] += b1.z; o[7] += b1.w;
            }
            if (RES) {
                const float* rp = resp + (long)gm * ldc + gnc;
                float4 r0 = *(const float4*)rp;
                float4 r1 = *(const float4*)(rp + 4);
                o[0] += r0.x; o[1] += r0.y; o[2] += r0.z; o[3] += r0.w;
                o[4] += r1.x; o[5] += r1.y; o[6] += r1.z; o[7] += r1.w;
            }
            if (EXPP) {
#pragma unroll
                for (int e = 0; e < 8; e++) { o[e] = __expf(o[e]); rs += o[e]; }
            }
            if (RSUM) {
                float inv = 1.0f / aux[bz * HW + gm];
#pragma unroll
                for (int e = 0; e < 8; e++) o[e] *= inv;
            }
            if (OBF) {
                __nv_bfloat16* cp = (__nv_bfloat16*)Cv + (long)bz * sC + (long)gm * ldc + gnc;
                __nv_bfloat162 p0 = __floats2bfloat162_rn(o[0], o[1]);
                __nv_bfloat162 p1 = __floats2bfloat162_rn(o[2], o[3]);
                __nv_bfloat162 p2 = __floats2bfloat162_rn(o[4], o[5]);
                __nv_bfloat162 p3 = __floats2bfloat162_rn(o[6], o[7]);
                uint4 u;
                u.x = *(unsigned*)&p0; u.y = *(unsigned*)&p1;
                u.z = *(unsigned*)&p2; u.w = *(unsigned*)&p3;
                *(uint4*)cp = u;
            } else {
                float* cp = (float*)Cv + (long)bz * sC + (long)gm * ldc + gnc;
                *(float4*)cp       = make_float4(o[0], o[1], o[2], o[3]);
                *(float4*)(cp + 4) = make_float4(o[4], o[5], o[6], o[7]);
            }
        }
        if (EXPP) {
            // combine lane pairs (same row, complementary 8-col blocks over j)
            rs += __shfl_xor_sync(0xFFFFFFFFu, rs, 1);
            if (!(lane & 1)) {
                const int tIdx = (bn + wn * 64) >> 6;          // 64-col tile index
                aux[((long)bz * 64 + tIdx) * HW + gm] = rs;
            }
        }
    }
}

// ---------------- launch ----------------
extern "C" void kernel_launch(void* const* d_in, const int* in_sizes, int n_in,
                              void* d_out, int out_size) {
    const float* x     = (const float*)d_in[0];
    const float* gamma = (const float*)d_in[1];
    const float* beta  = (const float*)d_in[2];
    const float* wq = (const float*)d_in[3];
    const float* bq = (const float*)d_in[4];
    const float* wk = (const float*)d_in[5];
    const float* bk = (const float*)d_in[6];
    const float* wv = (const float*)d_in[7];
    const float* bv = (const float*)d_in[8];
    const float* wp = (const float*)d_in[9];
    const float* bp = (const float*)d_in[10];
    float* out = (float*)d_out;

    __nv_bfloat16 *hh, *qkv, *ao, *pr, *wqkvp, *wpr;
    float *bqkvp, *psum, *rowsum;
    cudaGetSymbolAddress((void**)&hh, g_h);
    cudaGetSymbolAddress((void**)&qkv, g_qkv);
    cudaGetSymbolAddress((void**)&ao, g_ao);
    cudaGetSymbolAddress((void**)&pr, g_p);
    cudaGetSymbolAddress((void**)&wqkvp, g_wqkv);
    cudaGetSymbolAddress((void**)&bqkvp, g_bqkv);
    cudaGetSymbolAddress((void**)&wpr, g_wpr);
    cudaGetSymbolAddress((void**)&psum, g_psum);
    cudaGetSymbolAddress((void**)&rowsum, g_rowsum);

    cudaFuncSetAttribute(gemm_bf16<false, true,  false, true,  false, false>, cudaFuncAttributeMaxDynamicSharedMemorySize, SMEMSZ);
    cudaFuncSetAttribute(gemm_bf16<true,  false, false, true,  true,  false>, cudaFuncAttributeMaxDynamicSharedMemorySize, SMEMSZ);
    cudaFuncSetAttribute(gemm_bf16<false, false, false, true,  false, true >, cudaFuncAttributeMaxDynamicSharedMemorySize, SMEMSZ);
    cudaFuncSetAttribute(gemm_bf16<false, true,  true,  false, false, false>, cudaFuncAttributeMaxDynamicSharedMemorySize, SMEMSZ);

    const long sQ = (long)HW * QKVN;
    const long sS = (long)HW * HW;
    const long sO = (long)HW * CH;
    const float scale = 0.044194173824159216f;   // 1/sqrt(512)

    prep<<<(CH * QKVN + CH * CH) / 256, 256>>>(wq, wk, wv, wp, bq, bk, bv);

    gn_stats<<<NB * NGRP, 256>>>(x);
    gn_apply<<<(int)(((long)NB * HW * CH / 4) / 256), 256>>>(x, gamma, beta);

    // fused QKV: [16384,512] @ [512,1536] + bias -> bf16
    gemm_bf16<false, true, false, true, false, false>
        <<<dim3(QKVN / BN, (NB * HW) / BM, 1), 256, SMEMSZ>>>(
        hh, wqkvp, bqkvp, nullptr, nullptr, qkv, CH, QKVN, QKVN, 0, 0, 0, CH, 1.0f);

    // scores+exp: probs = exp(scale * q@k^T) -> bf16 (unnormalized) + row partials
    gemm_bf16<true, false, false, true, true, false>
        <<<dim3(HW / BN, HW / BM, NB), 256, SMEMSZ>>>(
        qkv, qkv + 512, nullptr, nullptr, psum, pr, QKVN, QKVN, HW, sQ, sQ, sS, CH, scale);

    // rowsum
    rowsum_reduce<<<(NB * HW) / 256, 256>>>();

    // attn @ v with rowsum normalization -> bf16
    gemm_bf16<false, false, false, true, false, true>
        <<<dim3(CH / BN, HW / BM, NB), 256, SMEMSZ>>>(
        pr, qkv + 1024, nullptr, nullptr, rowsum, ao, HW, QKVN, CH, sS, sQ, sO, HW, 1.0f);

    // proj + residual -> fp32 out
    gemm_bf16<false, true, true, false, false, false>
        <<<dim3(CH / BN, (NB * HW) / BM, 1), 256, SMEMSZ>>>(
        ao, wpr, bp, x, nullptr, out, CH, CH, CH, 0, 0, 0, CH, 1.0f);
}